// round 5
// baseline (speedup 1.0000x reference)
#include <cuda_runtime.h>
#include <cuda_fp16.h>

// Problem constants
#define NB   2
#define GG   8
#define HW   2304     // 48*48
#define DD   2116     // 46*46
#define KROWS 2176    // DD padded to chunk multiple (17*128)
#define VROWS 2120    // DD padded to 16B-multiple of halves

// ---------------- scratch (device globals; no allocation allowed) ----------------
__device__ float g_xh[NB][GG][128][HW];          // interleaved x(proj)/h per group (tf32)
__device__ float g_q [NB * GG * 64 * HW];        // q[head][c][pos]
__device__ float g_kt[NB * GG * KROWS * 64];     // k transposed [head][d][c], padded rows
__device__ __half g_vth[NB * GG * 64 * VROWS + 256]; // v [head][c][d] f16, padded
__device__ float g_at[NB * GG * HW * 64];        // a transposed [head][q][c]
__device__ float g_gx[4][NB * 512 * HW];         // 3x3 gate conv outputs (i,f,g,o)
__device__ float g_wproj[768 * 512];             // [ci][co]
__device__ float g_wc[7][GG][128][9][64];        // transposed 3x3 weights (tf32)
__device__ float g_wa[4][GG][64][64];            // gate 1x1 weights [gate][g][ci][co]

// ---------------- helpers ----------------
__device__ __forceinline__ float to_tf32(float x) {
    float y;
    asm("cvt.rna.tf32.f32 %0, %1;" : "=f"(y) : "f"(x));
    return y;
}

__device__ __forceinline__ void mma_tf32(float* d, const float* a, float b0, float b1) {
    asm volatile(
        "mma.sync.aligned.m16n8k8.row.col.f32.tf32.tf32.f32 "
        "{%0,%1,%2,%3}, {%4,%5,%6,%7}, {%8,%9}, {%0,%1,%2,%3};"
        : "+f"(d[0]), "+f"(d[1]), "+f"(d[2]), "+f"(d[3])
        : "r"(__float_as_uint(a[0])), "r"(__float_as_uint(a[1])),
          "r"(__float_as_uint(a[2])), "r"(__float_as_uint(a[3])),
          "r"(__float_as_uint(b0)), "r"(__float_as_uint(b1)));
}

__device__ __forceinline__ void mma_f16(float* d, const unsigned* a, unsigned b0, unsigned b1) {
    asm volatile(
        "mma.sync.aligned.m16n8k16.row.col.f32.f16.f16.f32 "
        "{%0,%1,%2,%3}, {%4,%5,%6,%7}, {%8,%9}, {%0,%1,%2,%3};"
        : "+f"(d[0]), "+f"(d[1]), "+f"(d[2]), "+f"(d[3])
        : "r"(a[0]), "r"(a[1]), "r"(a[2]), "r"(a[3]), "r"(b0), "r"(b1));
}

// pack two f32 (base-2 log domain) -> f16x2 -> 2^x
__device__ __forceinline__ unsigned exp2h2(float lo, float hi) {
    unsigned r;
    asm("{\n\t.reg .b32 t;\n\tcvt.rn.f16x2.f32 t, %2, %1;\n\tex2.approx.f16x2 %0, t;\n\t}"
        : "=r"(r) : "f"(lo), "f"(hi));
    return r;
}

__device__ __forceinline__ float ex2f(float x) {
    float y;
    asm("ex2.approx.ftz.f32 %0, %1;" : "=f"(y) : "f"(x));
    return y;
}

__device__ __forceinline__ void cp16(unsigned dst, const void* src) {
    asm volatile("cp.async.cg.shared.global [%0], [%1], 16;" :: "r"(dst), "l"(src));
}
#define CP_COMMIT() asm volatile("cp.async.commit_group;")
#define CP_WAIT(n)  asm volatile("cp.async.wait_group %0;" :: "n"(n))

// ---------------- init / weight prep ----------------
__global__ void zero_pad_k() {
    int i = blockIdx.x * 256 + threadIdx.x;
    const int nk = NB * GG * (KROWS - DD) * 64;   // 61440
    if (i < nk) {
        int c = i & 63;
        int r = (i >> 6) % (KROWS - DD);
        int hd = i / ((KROWS - DD) * 64);
        g_kt[(hd * KROWS + DD + r) * 64 + c] = 0.f;
    }
    const int nv = NB * GG * 64 * (VROWS - DD);   // 4096
    if (i < nv) {
        int p = i % (VROWS - DD);
        int row = i / (VROWS - DD);
        g_vth[row * VROWS + DD + p] = __float2half(0.f);
    }
    if (i < 256) g_vth[NB * GG * 64 * VROWS + i] = __float2half(0.f);
}

__global__ void prep_wproj_k(const float* __restrict__ Wx, const float* __restrict__ Wig) {
    int i = blockIdx.x * 256 + threadIdx.x;
    if (i >= 768 * 512) return;
    int ci = i >> 9, co = i & 511;
    g_wproj[i] = to_tf32((ci < 256) ? Wx[co * 256 + ci] : Wig[co * 512 + (ci - 256)]);
}

__global__ void prep_wc_all_k(const float* __restrict__ Wq, const float* __restrict__ Wk,
                              const float* __restrict__ Wv, const float* __restrict__ Wi,
                              const float* __restrict__ Wf, const float* __restrict__ Wg,
                              const float* __restrict__ Wo) {
    int slot = blockIdx.y;
    const float* W;
    switch (slot) {
        case 0: W = Wq; break; case 1: W = Wk; break; case 2: W = Wv; break;
        case 3: W = Wi; break; case 4: W = Wf; break; case 5: W = Wg; break;
        default: W = Wo; break;
    }
    int i = blockIdx.x * 256 + threadIdx.x;
    if (i >= GG * 128 * 9 * 64) return;
    int co = i & 63;
    int tap = (i >> 6) % 9;
    int ci = (i / 576) & 127;
    int g  = i / (576 * 128);
    g_wc[slot][g][ci][tap][co] = to_tf32(W[((g * 64 + co) * 128 + ci) * 9 + tap]);
}

__global__ void prep_wa_all_k(const float* __restrict__ Wi, const float* __restrict__ Wf,
                              const float* __restrict__ Wg, const float* __restrict__ Wo) {
    int slot = blockIdx.y;
    const float* W = (slot == 0) ? Wi : (slot == 1) ? Wf : (slot == 2) ? Wg : Wo;
    int i = blockIdx.x * 256 + threadIdx.x;
    if (i >= GG * 64 * 64) return;
    int co = i & 63;
    int ci = (i >> 6) & 63;
    int g  = i >> 12;
    g_wa[slot][g][ci][co] = W[(g * 64 + co) * 64 + ci];
}

__global__ void copy_h_k(const float* __restrict__ h) {
    int i = blockIdx.x * 256 + threadIdx.x;
    if (i >= NB * 512 * HW) return;
    int p  = i % HW;
    int ch = (i / HW) & 511;
    int n  = i / (512 * HW);
    g_xh[n][ch >> 6][64 + (ch & 63)][p] = to_tf32(h[i]);
}

// ---------------- proj 1x1 via tf32 mma ----------------
// grid (18, 8, NB), 256 threads. Block tile 128 px x 64 co, K = 768 ci.
#define PJ_PX 132
#define PJ_WS 68

__global__ void __launch_bounds__(256) projmma_k(const float* __restrict__ x_in,
                                                 const float* __restrict__ h) {
    __shared__ float s_in[16 * PJ_PX];
    __shared__ float s_w[16 * PJ_WS];
    int n = blockIdx.z, cot = blockIdx.y, pxt = blockIdx.x;
    int t = threadIdx.x, w = t >> 5, lane = t & 31;
    int grp = lane >> 2, tg = lane & 3;
    int pbase = pxt * 128;

    float acc[8][4];
#pragma unroll
    for (int nt = 0; nt < 8; nt++)
#pragma unroll
        for (int r = 0; r < 4; r++) acc[nt][r] = 0.f;

    for (int cb = 0; cb < 768; cb += 16) {
        for (int idx = t; idx < 2048; idx += 256) {
            int ci = idx >> 7, px = idx & 127;
            int cig = cb + ci;
            float v = (cig < 256) ? x_in[(n * 256 + cig) * HW + pbase + px]
                                  : h[(n * 512 + (cig - 256)) * HW + pbase + px];
            s_in[ci * PJ_PX + px] = to_tf32(v);
        }
        for (int idx = t; idx < 1024; idx += 256) {
            int ci = idx >> 6, co = idx & 63;
            s_w[ci * PJ_WS + co] = g_wproj[(cb + ci) * 512 + cot * 64 + co];
        }
        __syncthreads();
#pragma unroll
        for (int kc = 0; kc < 2; kc++) {
            float a[4];
            const float* ip = &s_in[(kc * 8 + tg) * PJ_PX + w * 16 + grp];
            a[0] = ip[0];
            a[1] = ip[8];
            a[2] = ip[4 * PJ_PX];
            a[3] = ip[4 * PJ_PX + 8];
#pragma unroll
            for (int nt = 0; nt < 8; nt++) {
                const float* wp = &s_w[(kc * 8 + tg) * PJ_WS + nt * 8 + grp];
                mma_tf32(acc[nt], a, wp[0], wp[4 * PJ_WS]);
            }
        }
        __syncthreads();
    }

    float* base = &g_xh[n][cot][0][0];
    int px0 = pbase + w * 16 + grp;
#pragma unroll
    for (int nt = 0; nt < 8; nt++) {
        int co = nt * 8 + 2 * tg;
        base[co * HW + px0]           = to_tf32(acc[nt][0]);
        base[(co + 1) * HW + px0]     = to_tf32(acc[nt][1]);
        base[co * HW + px0 + 8]       = to_tf32(acc[nt][2]);
        base[(co + 1) * HW + px0 + 8] = to_tf32(acc[nt][3]);
    }
}

// ---------------- grouped 3x3 conv via tf32 mma.sync (implicit GEMM) ----------------
#define IN_CI 360
#define IN_ROW 20
#define W_TAP 576
#define W_CI 72

__global__ void __launch_bounds__(256) conv3mma_k(int mode) {
    __shared__ float s_in[8 * IN_CI];
    __shared__ float s_w[9 * W_TAP];

    int g = blockIdx.y;
    int n, slot, OW, pad;
    if (mode == 0) {
        int sl = blockIdx.z % 5;
        n = blockIdx.z / 5;
        slot = (sl == 0) ? 0 : (sl + 2);
        OW = 48; pad = 1;
    } else {
        n = blockIdx.z >> 1;
        slot = 1 + (blockIdx.z & 1);
        OW = 46; pad = 0;
    }

    int ty0 = (blockIdx.x / 3) * 16, tx0 = (blockIdx.x % 3) * 16;
    int t = threadIdx.x;
    int w = t >> 5, lane = t & 31;
    int pxg = w & 3, cog = w >> 2;
    int grp = lane >> 2, tg = lane & 3;

    float acc[4][4][4];
#pragma unroll
    for (int m = 0; m < 4; m++)
#pragma unroll
        for (int nt = 0; nt < 4; nt++)
#pragma unroll
            for (int r = 0; r < 4; r++) acc[m][nt][r] = 0.f;

    const float* xh = &g_xh[n][g][0][0];
    const float* wt = &g_wc[slot][g][0][0][0];

    for (int cb = 0; cb < 128; cb += 8) {
        for (int idx = t; idx < 8 * 324; idx += 256) {
            int ci = idx / 324;
            int rem = idx - ci * 324;
            int rr = rem / 18;
            int cc = rem - rr * 18;
            int iy = ty0 - pad + rr, ix = tx0 - pad + cc;
            float vv = 0.f;
            if ((unsigned)iy < 48u && (unsigned)ix < 48u)
                vv = xh[(cb + ci) * HW + iy * 48 + ix];
            s_in[ci * IN_CI + rr * IN_ROW + cc] = vv;
        }
        for (int idx = t; idx < 4608; idx += 256) {
            int co = idx & 63;
            int rest = idx >> 6;
            int ci = rest & 7;
            int tap = rest >> 3;
            s_w[tap * W_TAP + ci * W_CI + co] = wt[(cb + ci) * 576 + tap * 64 + co];
        }
        __syncthreads();

#pragma unroll
        for (int kh = 0; kh < 3; kh++) {
#pragma unroll
            for (int kw = 0; kw < 3; kw++) {
                float a[4][4];
#pragma unroll
                for (int m = 0; m < 4; m++) {
                    const float* p0 = &s_in[tg * IN_CI + (pxg * 4 + m + kh) * IN_ROW + grp + kw];
                    a[m][0] = p0[0];
                    a[m][1] = p0[8];
                    a[m][2] = p0[4 * IN_CI];
                    a[m][3] = p0[4 * IN_CI + 8];
                }
                const float* wp = &s_w[(kh * 3 + kw) * W_TAP + tg * W_CI + cog * 32 + grp];
#pragma unroll
                for (int nt = 0; nt < 4; nt++) {
                    float b0 = wp[nt * 8];
                    float b1 = wp[4 * W_CI + nt * 8];
#pragma unroll
                    for (int m = 0; m < 4; m++) mma_tf32(acc[m][nt], a[m], b0, b1);
                }
            }
        }
        __syncthreads();
    }

    int hbase = n * GG + g;
#pragma unroll
    for (int m = 0; m < 4; m++) {
        int y = ty0 + pxg * 4 + m;
#pragma unroll
        for (int nt = 0; nt < 4; nt++) {
            int co = cog * 32 + nt * 8 + 2 * tg;
            int x1 = tx0 + grp, x2 = x1 + 8;
            if (mode == 1) {
                if (y < 46) {
                    if (slot == 1) {  // K -> g_kt [head][d pad KROWS][c]
                        if (x1 < 46) {
                            float2 v = {acc[m][nt][0], acc[m][nt][1]};
                            *(float2*)&g_kt[((size_t)hbase * KROWS + y * 46 + x1) * 64 + co] = v;
                        }
                        if (x2 < 46) {
                            float2 v = {acc[m][nt][2], acc[m][nt][3]};
                            *(float2*)&g_kt[((size_t)hbase * KROWS + y * 46 + x2) * 64 + co] = v;
                        }
                    } else {          // V -> g_vth [head][c][d pad VROWS] f16
                        if (x1 < 46) {
                            int d = y * 46 + x1;
                            g_vth[(size_t)(hbase * 64 + co) * VROWS + d] = __float2half(acc[m][nt][0]);
                            g_vth[(size_t)(hbase * 64 + co + 1) * VROWS + d] = __float2half(acc[m][nt][1]);
                        }
                        if (x2 < 46) {
                            int d = y * 46 + x2;
                            g_vth[(size_t)(hbase * 64 + co) * VROWS + d] = __float2half(acc[m][nt][2]);
                            g_vth[(size_t)(hbase * 64 + co + 1) * VROWS + d] = __float2half(acc[m][nt][3]);
                        }
                    }
                }
            } else {
                float* ob = (slot == 0) ? g_q : &g_gx[slot - 3][0];
                ob += (size_t)hbase * 64 * HW + y * 48;
                ob[co * HW + x1] = acc[m][nt][0];
                ob[(co + 1) * HW + x1] = acc[m][nt][1];
                ob[co * HW + x2] = acc[m][nt][2];
                ob[(co + 1) * HW + x2] = acc[m][nt][3];
            }
        }
    }
}

// ---------------- flash attention: tf32 QK, f16 PV, cp.async double-buffer ----------------
// 256 threads (8 warps), 128 queries per block. Warp = 16 q x full 128-key width.
// S C-fragment feeds f16 PV A-fragment directly (no shuffles, no sP).
// Row-sum l via ones-column in V (9th n-tile).
#define QS 68
#define KS 68
#define VS 136   // halves
#define SK_OFF 8704
#define SV_OFF (8704 + 2 * 8704)
#define ATTN_SMEM (SV_OFF * 4 + 2 * 9792 * 2)

__global__ void __launch_bounds__(256) attn_k(const float* __restrict__ tau) {
    extern __shared__ float sm[];
    float* sQ = sm;
    float* sK = sm + SK_OFF;                       // [2][128][KS]
    __half* sVh = (__half*)(sm + SV_OFF);          // [2][72][VS]

    int n = blockIdx.z, g = blockIdx.y;
    int head = n * GG + g;
    int q0 = blockIdx.x * 128;
    int t = threadIdx.x, w = t >> 5, lane = t & 31;
    int grp = lane >> 2, tg = lane & 3;
    int qb = w * 16;
    float tl = tau[g] * 1.44269504f;   // fold log2(e) into logits

    unsigned sK_u = (unsigned)__cvta_generic_to_shared(sK);
    unsigned sV_u = (unsigned)__cvta_generic_to_shared(sVh);

    // stage Q (scaled)
    for (int idx = t; idx < 8192; idx += 256) {
        int c = idx >> 7, qq = idx & 127;
        sQ[qq * QS + c] = g_q[(head * 64 + c) * HW + q0 + qq] * tl;
    }
    // ones/zeros rows 64..71 of both V buffers (row 64 = ones -> l column)
    for (int idx = t; idx < 2 * 8 * VS; idx += 256) {
        int buf = idx / (8 * VS);
        int r = idx % (8 * VS);
        int row = 64 + r / VS, col = r % VS;
        sVh[buf * 9792 + row * VS + col] = __float2half(row == 64 ? 1.f : 0.f);
    }

    auto stage = [&](int ch, int buf) {
        int db = ch * 128;
        const float* ksrc = g_kt + ((size_t)head * KROWS + db) * 64;
        for (int idx = t; idx < 2048; idx += 256) {
            int d = idx >> 4, seg = idx & 15;
            cp16(sK_u + (buf * 8704 + d * KS + seg * 4) * 4, ksrc + d * 64 + seg * 4);
        }
        const __half* vsrc = g_vth + (size_t)head * 64 * VROWS + db;
        for (int idx = t; idx < 1024; idx += 256) {
            int c = idx >> 4, seg = idx & 15;
            cp16(sV_u + (buf * 9792 + c * VS + seg * 8) * 2, vsrc + (size_t)c * VROWS + seg * 8);
        }
    };

    stage(0, 0);
    CP_COMMIT();
    __syncthreads();

    // resident Q fragments
    float aQ[8][4];
#pragma unroll
    for (int kc = 0; kc < 8; kc++) {
        const float* p = &sQ[(qb + grp) * QS + kc * 8 + tg];
        aQ[kc][0] = p[0];
        aQ[kc][1] = p[8 * QS];
        aQ[kc][2] = p[4];
        aQ[kc][3] = p[8 * QS + 4];
    }

    float O[9][4];
#pragma unroll
    for (int nt = 0; nt < 9; nt++)
#pragma unroll
        for (int r = 0; r < 4; r++) O[nt][r] = 0.f;
    float m0 = -1e30f, m1 = -1e30f;

    const int nch = KROWS / 128;   // 17
    for (int ch = 0; ch < nch; ch++) {
        int buf = ch & 1;
        if (ch + 1 < nch) {
            stage(ch + 1, buf ^ 1);
            CP_COMMIT();
            CP_WAIT(1);
        } else {
            CP_WAIT(0);
        }
        __syncthreads();

        const float* sKb = sK + buf * 8704;
        const __half* sVb = sVh + buf * 9792;

        // S = Q K^T : 16 q x 128 keys per warp
        float S[16][4];
#pragma unroll
        for (int nt = 0; nt < 16; nt++) {
            S[nt][0] = S[nt][1] = S[nt][2] = S[nt][3] = 0.f;
#pragma unroll
            for (int kc = 0; kc < 8; kc++) {
                const float* bp = &sKb[(nt * 8 + grp) * KS + kc * 8 + tg];
                mma_tf32(S[nt], aQ[kc], bp[0], bp[4]);
            }
        }

        if (ch == nch - 1) {
            int cb = ch * 128 + 2 * tg;
#pragma unroll
            for (int nt = 0; nt < 16; nt++) {
                int c = cb + nt * 8;
                if (c >= DD)     { S[nt][0] = -1e30f; S[nt][2] = -1e30f; }
                if (c + 1 >= DD) { S[nt][1] = -1e30f; S[nt][3] = -1e30f; }
            }
        }

        // online softmax (base-2 domain)
        float rm0 = -1e30f, rm1 = -1e30f;
#pragma unroll
        for (int nt = 0; nt < 16; nt++) {
            rm0 = fmaxf(rm0, fmaxf(S[nt][0], S[nt][1]));
            rm1 = fmaxf(rm1, fmaxf(S[nt][2], S[nt][3]));
        }
        rm0 = fmaxf(rm0, __shfl_xor_sync(0xffffffffu, rm0, 1));
        rm0 = fmaxf(rm0, __shfl_xor_sync(0xffffffffu, rm0, 2));
        rm1 = fmaxf(rm1, __shfl_xor_sync(0xffffffffu, rm1, 1));
        rm1 = fmaxf(rm1, __shfl_xor_sync(0xffffffffu, rm1, 2));
        float mn0 = fmaxf(m0, rm0), mn1 = fmaxf(m1, rm1);
        float a0 = ex2f(m0 - mn0), a1 = ex2f(m1 - mn1);
        m0 = mn0; m1 = mn1;
#pragma unroll
        for (int nt = 0; nt < 9; nt++) {
            O[nt][0] *= a0; O[nt][1] *= a0;
            O[nt][2] *= a1; O[nt][3] *= a1;
        }

        // P = 2^(S-m) in f16x2 — lands directly in mma A-fragment layout
        unsigned pf[16][2];
#pragma unroll
        for (int nt = 0; nt < 16; nt++) {
            pf[nt][0] = exp2h2(S[nt][0] - m0, S[nt][1] - m0);
            pf[nt][1] = exp2h2(S[nt][2] - m1, S[nt][3] - m1);
        }

        // O += P V (f16 mma, k=16); nt=8 n-tile accumulates l via ones column
#pragma unroll
        for (int kc = 0; kc < 8; kc++) {
            unsigned A4[4] = {pf[2 * kc][0], pf[2 * kc][1], pf[2 * kc + 1][0], pf[2 * kc + 1][1]};
#pragma unroll
            for (int nt = 0; nt < 9; nt++) {
                const __half* vp = &sVb[(nt * 8 + grp) * VS + kc * 16 + 2 * tg];
                unsigned b0 = *(const unsigned*)vp;
                unsigned b1 = *(const unsigned*)(vp + 8);
                mma_f16(O[nt], A4, b0, b1);
            }
        }
        __syncthreads();
    }

    // l lives in col 64 -> tg==0 lanes; broadcast within quad
    float l0 = __shfl_sync(0xffffffffu, O[8][0], lane & ~3);
    float l1 = __shfl_sync(0xffffffffu, O[8][2], lane & ~3);
    float inv0 = 1.f / l0, inv1 = 1.f / l1;
#pragma unroll
    for (int nt = 0; nt < 8; nt++) {
        int c = nt * 8 + 2 * tg;
        float2 v0 = {O[nt][0] * inv0, O[nt][1] * inv0};
        float2 v1 = {O[nt][2] * inv1, O[nt][3] * inv1};
        *(float2*)&g_at[((size_t)head * HW + q0 + qb + grp) * 64 + c] = v0;
        *(float2*)&g_at[((size_t)head * HW + q0 + qb + grp + 8) * 64 + c] = v1;
    }
}

// ---------------- final: gate 1x1 + bias + gx + LSTM update ----------------
__device__ __forceinline__ float tanh_fast(float x) {
    float e = __expf(-2.f * fabsf(x));
    float r = (1.f - e) / (1.f + e);
    return copysignf(r, x);
}

__global__ void __launch_bounds__(256) final_k(const float* __restrict__ c_in,
                                               const float* __restrict__ b_i,
                                               const float* __restrict__ b_f,
                                               const float* __restrict__ b_g,
                                               const float* __restrict__ b_o,
                                               float* __restrict__ out) {
    extern __shared__ float s_wa[];  // [4][64][64]
    int n = blockIdx.z, g = blockIdx.y, pxt = blockIdx.x;
    int t = threadIdx.x;
    int head = n * GG + g;
    int px = pxt * 256 + t;

    const float* wa_flat = (const float*)g_wa;
    for (int idx = t; idx < 4 * 64 * 64; idx += 256) {
        int s = idx >> 12, r = idx & 4095;
        s_wa[idx] = wa_flat[s * (GG * 4096) + g * 4096 + r];
    }
    __syncthreads();

    float av[64];
    const float4* ap = (const float4*)&g_at[((size_t)head * HW + px) * 64];
#pragma unroll
    for (int c4 = 0; c4 < 16; c4++) {
        float4 v = ap[c4];
        av[c4 * 4 + 0] = v.x;
        av[c4 * 4 + 1] = v.y;
        av[c4 * 4 + 2] = v.z;
        av[c4 * 4 + 3] = v.w;
    }

    for (int co = 0; co < 64; co++) {
        float ai = 0.f, af = 0.f, ag = 0.f, ao = 0.f;
#pragma unroll 16
        for (int ci = 0; ci < 64; ci++) {
            float a = av[ci];
            ai += s_wa[0 * 4096 + ci * 64 + co] * a;
            af += s_wa[1 * 4096 + ci * 64 + co] * a;
            ag += s_wa[2 * 4096 + ci * 64 + co] * a;
            ao += s_wa[3 * 4096 + ci * 64 + co] * a;
        }
        int ch = g * 64 + co;
        int gi = (n * 512 + ch) * HW + px;
        ai += b_i[ch] + g_gx[0][gi];
        af += b_f[ch] + g_gx[1][gi];
        ag += b_g[ch] + g_gx[2][gi];
        ao += b_o[ch] + g_gx[3][gi];
        float iv = 1.f / (1.f + __expf(-ai));
        float fv = 1.f / (1.f + __expf(-af));
        float gv = tanh_fast(ag);
        float ov = 1.f / (1.f + __expf(-ao));
        float cn = fv * c_in[gi] + iv * gv;
        out[gi] = ov * tanh_fast(cn);
    }
}

// ---------------- launch ----------------
extern "C" void kernel_launch(void* const* d_in, const int* in_sizes, int n_in,
                              void* d_out, int out_size) {
    const float* x_in = (const float*)d_in[0];
    const float* h    = (const float*)d_in[1];
    const float* c    = (const float*)d_in[2];
    const float* tau  = (const float*)d_in[3];
    const float* W_x  = (const float*)d_in[4];
    const float* W_ig = (const float*)d_in[5];
    const float* W_q  = (const float*)d_in[6];
    const float* W_k  = (const float*)d_in[7];
    const float* W_v  = (const float*)d_in[8];
    const float* Wi_a = (const float*)d_in[9];
    const float* Wi_x = (const float*)d_in[10];
    const float* b_i  = (const float*)d_in[11];
    const float* Wf_a = (const float*)d_in[12];
    const float* Wf_x = (const float*)d_in[13];
    const float* b_f  = (const float*)d_in[14];
    const float* Wg_a = (const float*)d_in[15];
    const float* Wg_x = (const float*)d_in[16];
    const float* b_g  = (const float*)d_in[17];
    const float* Wo_a = (const float*)d_in[18];
    const float* Wo_x = (const float*)d_in[19];
    const float* b_o  = (const float*)d_in[20];
    float* out = (float*)d_out;

    cudaFuncSetAttribute(attn_k, cudaFuncAttributeMaxDynamicSharedMemorySize, ATTN_SMEM);
    cudaFuncSetAttribute(final_k, cudaFuncAttributeMaxDynamicSharedMemorySize, 4 * 64 * 64 * 4);

    zero_pad_k<<<(NB * GG * (KROWS - DD) * 64 + 255) / 256, 256>>>();
    prep_wproj_k<<<(768 * 512 + 255) / 256, 256>>>(W_x, W_ig);
    prep_wc_all_k<<<dim3((8 * 128 * 9 * 64 + 255) / 256, 7), 256>>>(W_q, W_k, W_v,
                                                                    Wi_x, Wf_x, Wg_x, Wo_x);
    prep_wa_all_k<<<dim3((8 * 64 * 64 + 255) / 256, 4), 256>>>(Wi_a, Wf_a, Wg_a, Wo_a);

    copy_h_k<<<(NB * 512 * HW + 255) / 256, 256>>>(h);
    projmma_k<<<dim3(18, 8, NB), 256>>>(x_in, h);

    conv3mma_k<<<dim3(9, GG, NB * 5), 256>>>(0);   // q + 4 gates
    conv3mma_k<<<dim3(9, GG, NB * 2), 256>>>(1);   // k, v

    attn_k<<<dim3(HW / 128, GG, NB), 256, ATTN_SMEM>>>(tau);

    final_k<<<dim3(9, GG, NB), 256, 4 * 64 * 64 * 4>>>(c, b_i, b_f, b_g, b_o, out);
}

// round 6
// speedup vs baseline: 1.4970x; 1.4970x over previous
#include <cuda_runtime.h>
#include <cuda_fp16.h>

// Problem constants
#define NB   2
#define GG   8
#define HW   2304     // 48*48
#define DD   2116     // 46*46
#define KROWS 2176    // DD padded to chunk multiple (17*128)
#define VROWS 2120    // DD padded for f16 16B alignment

// ---------------- scratch (device globals; no allocation allowed) ----------------
__device__ __align__(256) __half g_xh16[NB][GG][HW][128];    // xh f16, channel-contiguous
__device__ float g_q [NB * GG * 64 * HW];                    // q [head][c][px]
__device__ float g_kt[NB * GG * KROWS * 64];                 // k [head][d][c], padded rows
__device__ __half g_vth[NB * GG * 64 * VROWS + 256];         // v [head][c][d] f16
__device__ float g_at[NB * GG * HW * 64];                    // a [head][q][c]
__device__ float g_gx[4][NB * 512 * HW];                     // gate conv outputs
__device__ float g_wproj[768 * 512];                         // [ci][co]
__device__ __align__(256) __half g_wc16[7][GG][8][9][64][16]; // [slot][g][cb16][tap][co][ci16]
__device__ float g_wa[4][GG][64][64];                        // gate 1x1 [gate][g][ci][co]

// ---------------- helpers ----------------
__device__ __forceinline__ float to_tf32(float x) {
    float y;
    asm("cvt.rna.tf32.f32 %0, %1;" : "=f"(y) : "f"(x));
    return y;
}

__device__ __forceinline__ void mma_tf32(float* d, const float* a, float b0, float b1) {
    asm volatile(
        "mma.sync.aligned.m16n8k8.row.col.f32.tf32.tf32.f32 "
        "{%0,%1,%2,%3}, {%4,%5,%6,%7}, {%8,%9}, {%0,%1,%2,%3};"
        : "+f"(d[0]), "+f"(d[1]), "+f"(d[2]), "+f"(d[3])
        : "r"(__float_as_uint(a[0])), "r"(__float_as_uint(a[1])),
          "r"(__float_as_uint(a[2])), "r"(__float_as_uint(a[3])),
          "r"(__float_as_uint(b0)), "r"(__float_as_uint(b1)));
}

__device__ __forceinline__ void mma_f16(float* d, const unsigned* a, unsigned b0, unsigned b1) {
    asm volatile(
        "mma.sync.aligned.m16n8k16.row.col.f32.f16.f16.f32 "
        "{%0,%1,%2,%3}, {%4,%5,%6,%7}, {%8,%9}, {%0,%1,%2,%3};"
        : "+f"(d[0]), "+f"(d[1]), "+f"(d[2]), "+f"(d[3])
        : "r"(a[0]), "r"(a[1]), "r"(a[2]), "r"(a[3]), "r"(b0), "r"(b1));
}

__device__ __forceinline__ void ldsm4(unsigned& r0, unsigned& r1, unsigned& r2, unsigned& r3,
                                      unsigned a) {
    asm volatile("ldmatrix.sync.aligned.m8n8.x4.shared.b16 {%0,%1,%2,%3}, [%4];"
                 : "=r"(r0), "=r"(r1), "=r"(r2), "=r"(r3) : "r"(a));
}
__device__ __forceinline__ void ldsm2(unsigned& r0, unsigned& r1, unsigned a) {
    asm volatile("ldmatrix.sync.aligned.m8n8.x2.shared.b16 {%0,%1}, [%2];"
                 : "=r"(r0), "=r"(r1) : "r"(a));
}

__device__ __forceinline__ unsigned exp2h2(float lo, float hi) {
    unsigned r;
    asm("{\n\t.reg .b32 t;\n\tcvt.rn.f16x2.f32 t, %2, %1;\n\tex2.approx.f16x2 %0, t;\n\t}"
        : "=r"(r) : "f"(lo), "f"(hi));
    return r;
}
__device__ __forceinline__ float ex2f(float x) {
    float y;
    asm("ex2.approx.ftz.f32 %0, %1;" : "=f"(y) : "f"(x));
    return y;
}

__device__ __forceinline__ void cp16(unsigned dst, const void* src) {
    asm volatile("cp.async.cg.shared.global [%0], [%1], 16;" :: "r"(dst), "l"(src));
}
__device__ __forceinline__ void cp16p(unsigned dst, const void* src, int sz) {
    asm volatile("cp.async.cg.shared.global [%0], [%1], 16, %2;" :: "r"(dst), "l"(src), "r"(sz));
}
#define CP_COMMIT() asm volatile("cp.async.commit_group;")
#define CP_WAIT(n)  asm volatile("cp.async.wait_group %0;" :: "n"(n))

// ---------------- init / weight prep ----------------
__global__ void zero_pad_k() {
    int i = blockIdx.x * 256 + threadIdx.x;
    const int nk = NB * GG * (KROWS - DD) * 64;
    if (i < nk) {
        int c = i & 63;
        int r = (i >> 6) % (KROWS - DD);
        int hd = i / ((KROWS - DD) * 64);
        g_kt[(hd * KROWS + DD + r) * 64 + c] = 0.f;
    }
    const int nv = NB * GG * 64 * (VROWS - DD);
    if (i < nv) {
        int p = i % (VROWS - DD);
        int row = i / (VROWS - DD);
        g_vth[row * VROWS + DD + p] = __float2half(0.f);
    }
    if (i < 256) g_vth[NB * GG * 64 * VROWS + i] = __float2half(0.f);
}

__global__ void prep_wproj_k(const float* __restrict__ Wx, const float* __restrict__ Wig) {
    int i = blockIdx.x * 256 + threadIdx.x;
    if (i >= 768 * 512) return;
    int ci = i >> 9, co = i & 511;
    g_wproj[i] = to_tf32((ci < 256) ? Wx[co * 256 + ci] : Wig[co * 512 + (ci - 256)]);
}

__global__ void prep_wc_all_k(const float* __restrict__ Wq, const float* __restrict__ Wk,
                              const float* __restrict__ Wv, const float* __restrict__ Wi,
                              const float* __restrict__ Wf, const float* __restrict__ Wg,
                              const float* __restrict__ Wo) {
    int slot = blockIdx.y;
    const float* W;
    switch (slot) {
        case 0: W = Wq; break; case 1: W = Wk; break; case 2: W = Wv; break;
        case 3: W = Wi; break; case 4: W = Wf; break; case 5: W = Wg; break;
        default: W = Wo; break;
    }
    int i = blockIdx.x * 256 + threadIdx.x;
    if (i >= GG * 128 * 9 * 64) return;
    int co = i & 63;
    int tap = (i >> 6) % 9;
    int ci = (i / 576) & 127;
    int g  = i / (576 * 128);
    g_wc16[slot][g][ci >> 4][tap][co][ci & 15] =
        __float2half(W[((g * 64 + co) * 128 + ci) * 9 + tap]);
}

__global__ void prep_wa_all_k(const float* __restrict__ Wi, const float* __restrict__ Wf,
                              const float* __restrict__ Wg, const float* __restrict__ Wo) {
    int slot = blockIdx.y;
    const float* W = (slot == 0) ? Wi : (slot == 1) ? Wf : (slot == 2) ? Wg : Wo;
    int i = blockIdx.x * 256 + threadIdx.x;
    if (i >= GG * 64 * 64) return;
    int co = i & 63;
    int ci = (i >> 6) & 63;
    int g  = i >> 12;
    g_wa[slot][g][ci][co] = W[(g * 64 + co) * 64 + ci];
}

// h -> xh upper half, transposed to channel-contiguous f16
__global__ void __launch_bounds__(256) copy_hxT_k(const float* __restrict__ h) {
    int n = blockIdx.z, g = blockIdx.y;
    int px = blockIdx.x * 256 + threadIdx.x;
    __half2* dst = (__half2*)&g_xh16[n][g][px][64];
    const float* hb = h + (n * 512 + g * 64) * HW + px;
#pragma unroll 8
    for (int c2 = 0; c2 < 32; c2++) {
        float a = hb[(2 * c2) * HW];
        float b = hb[(2 * c2 + 1) * HW];
        dst[c2] = __floats2half2_rn(a, b);
    }
}

// ---------------- proj 1x1 via tf32 mma -> xh lower half (f16, [px][c]) ----------------
#define PJ_PX 132
#define PJ_WS 68

__global__ void __launch_bounds__(256) projmma_k(const float* __restrict__ x_in,
                                                 const float* __restrict__ h) {
    __shared__ float s_in[16 * PJ_PX];
    __shared__ float s_w[16 * PJ_WS];
    int n = blockIdx.z, cot = blockIdx.y, pxt = blockIdx.x;
    int t = threadIdx.x, w = t >> 5, lane = t & 31;
    int grp = lane >> 2, tg = lane & 3;
    int pbase = pxt * 128;

    float acc[8][4];
#pragma unroll
    for (int nt = 0; nt < 8; nt++)
#pragma unroll
        for (int r = 0; r < 4; r++) acc[nt][r] = 0.f;

    for (int cb = 0; cb < 768; cb += 16) {
        for (int idx = t; idx < 2048; idx += 256) {
            int ci = idx >> 7, px = idx & 127;
            int cig = cb + ci;
            float v = (cig < 256) ? x_in[(n * 256 + cig) * HW + pbase + px]
                                  : h[(n * 512 + (cig - 256)) * HW + pbase + px];
            s_in[ci * PJ_PX + px] = to_tf32(v);
        }
        for (int idx = t; idx < 1024; idx += 256) {
            int ci = idx >> 6, co = idx & 63;
            s_w[ci * PJ_WS + co] = g_wproj[(cb + ci) * 512 + cot * 64 + co];
        }
        __syncthreads();
#pragma unroll
        for (int kc = 0; kc < 2; kc++) {
            float a[4];
            const float* ip = &s_in[(kc * 8 + tg) * PJ_PX + w * 16 + grp];
            a[0] = ip[0];
            a[1] = ip[8];
            a[2] = ip[4 * PJ_PX];
            a[3] = ip[4 * PJ_PX + 8];
#pragma unroll
            for (int nt = 0; nt < 8; nt++) {
                const float* wp = &s_w[(kc * 8 + tg) * PJ_WS + nt * 8 + grp];
                mma_tf32(acc[nt], a, wp[0], wp[4 * PJ_WS]);
            }
        }
        __syncthreads();
    }

    __half* xb = &g_xh16[n][cot][0][0];
    int px0 = pbase + w * 16 + grp;
#pragma unroll
    for (int nt = 0; nt < 8; nt++) {
        int co = nt * 8 + 2 * tg;
        *(__half2*)&xb[(size_t)px0 * 128 + co]       = __floats2half2_rn(acc[nt][0], acc[nt][1]);
        *(__half2*)&xb[(size_t)(px0 + 8) * 128 + co] = __floats2half2_rn(acc[nt][2], acc[nt][3]);
    }
}

// ---------------- grouped 3x3 conv via f16 mma + ldmatrix + cp.async ----------------
#define IN_PITCH 24
#define IN_BUF (324 * IN_PITCH)   // halves
#define W_PITCH 24
#define W_BUF (576 * W_PITCH)     // halves
#define CONV_SMEM ((2 * IN_BUF + 2 * W_BUF) * 2)

__global__ void __launch_bounds__(256) conv3mma_k(int mode) {
    extern __shared__ __half smc[];
    unsigned su_in = (unsigned)__cvta_generic_to_shared(smc);
    unsigned su_w  = su_in + 2 * IN_BUF * 2;

    int g = blockIdx.y;
    int n, slot, pad;
    if (mode == 0) {
        int sl = blockIdx.z % 5;
        n = blockIdx.z / 5;
        slot = (sl == 0) ? 0 : (sl + 2);
        pad = 1;
    } else {
        n = blockIdx.z >> 1;
        slot = 1 + (blockIdx.z & 1);
        pad = 0;
    }

    int ty0 = (blockIdx.x / 3) * 16, tx0 = (blockIdx.x % 3) * 16;
    int t = threadIdx.x, w = t >> 5, lane = t & 31;
    int pxg = w & 3, cog = w >> 2;
    int grp = lane >> 2, tg = lane & 3;

    float acc[4][4][4];
#pragma unroll
    for (int m = 0; m < 4; m++)
#pragma unroll
        for (int nt = 0; nt < 4; nt++)
#pragma unroll
            for (int r = 0; r < 4; r++) acc[m][nt][r] = 0.f;

    const __half* xb = &g_xh16[n][g][0][0];

    auto stage = [&](int it, int buf) {
        int cb = it * 16;
        for (int r = t; r < 324; r += 256) {
            int y = r / 18, x = r - y * 18;
            int iy = ty0 - pad + y, ix = tx0 - pad + x;
            bool ok = ((unsigned)iy < 48u) && ((unsigned)ix < 48u);
            const __half* src = xb + (size_t)(ok ? iy * 48 + ix : 0) * 128 + cb;
            unsigned d = su_in + (buf * IN_BUF + r * IN_PITCH) * 2;
            int sz = ok ? 16 : 0;
            cp16p(d, src, sz);
            cp16p(d + 16, src + 8, sz);
        }
        const __half* wb = &g_wc16[slot][g][it][0][0][0];
        for (int r = t; r < 576; r += 256) {
            unsigned d = su_w + (buf * W_BUF + r * W_PITCH) * 2;
            cp16(d, wb + r * 16);
            cp16(d + 16, wb + r * 16 + 8);
        }
    };

    stage(0, 0);
    CP_COMMIT();
    for (int it = 0; it < 8; it++) {
        int buf = it & 1;
        if (it + 1 < 8) { stage(it + 1, buf ^ 1); CP_COMMIT(); CP_WAIT(1); }
        else CP_WAIT(0);
        __syncthreads();

        unsigned bi = su_in + buf * IN_BUF * 2;
        unsigned bw = su_w + buf * W_BUF * 2;
#pragma unroll
        for (int kh = 0; kh < 3; kh++) {
#pragma unroll
            for (int kw = 0; kw < 3; kw++) {
                unsigned b[4][2];
#pragma unroll
                for (int nt = 0; nt < 4; nt++) {
                    unsigned addr = bw + (((kh * 3 + kw) * 64 + cog * 32 + nt * 8 + (lane & 7))
                                          * W_PITCH + ((lane >> 3) & 1) * 8) * 2;
                    ldsm2(b[nt][0], b[nt][1], addr);
                }
#pragma unroll
                for (int m = 0; m < 4; m++) {
                    int py = pxg * 4 + m;
                    unsigned a[4];
                    unsigned addr = bi + (((py + kh) * 18 + (lane & 15) + kw) * IN_PITCH
                                          + (lane >> 4) * 8) * 2;
                    ldsm4(a[0], a[1], a[2], a[3], addr);
#pragma unroll
                    for (int nt = 0; nt < 4; nt++) mma_f16(acc[m][nt], a, b[nt][0], b[nt][1]);
                }
            }
        }
        __syncthreads();
    }

    int hbase = n * GG + g;
#pragma unroll
    for (int m = 0; m < 4; m++) {
        int y = ty0 + pxg * 4 + m;
#pragma unroll
        for (int nt = 0; nt < 4; nt++) {
            int co = cog * 32 + nt * 8 + 2 * tg;
            int x1 = tx0 + grp, x2 = x1 + 8;
            if (mode == 1) {
                if (y < 46) {
                    if (slot == 1) {
                        if (x1 < 46) {
                            float2 v = {acc[m][nt][0], acc[m][nt][1]};
                            *(float2*)&g_kt[((size_t)hbase * KROWS + y * 46 + x1) * 64 + co] = v;
                        }
                        if (x2 < 46) {
                            float2 v = {acc[m][nt][2], acc[m][nt][3]};
                            *(float2*)&g_kt[((size_t)hbase * KROWS + y * 46 + x2) * 64 + co] = v;
                        }
                    } else {
                        if (x1 < 46) {
                            int d = y * 46 + x1;
                            g_vth[(size_t)(hbase * 64 + co) * VROWS + d] = __float2half(acc[m][nt][0]);
                            g_vth[(size_t)(hbase * 64 + co + 1) * VROWS + d] = __float2half(acc[m][nt][1]);
                        }
                        if (x2 < 46) {
                            int d = y * 46 + x2;
                            g_vth[(size_t)(hbase * 64 + co) * VROWS + d] = __float2half(acc[m][nt][2]);
                            g_vth[(size_t)(hbase * 64 + co + 1) * VROWS + d] = __float2half(acc[m][nt][3]);
                        }
                    }
                }
            } else {
                float* ob = (slot == 0) ? g_q : &g_gx[slot - 3][0];
                ob += (size_t)hbase * 64 * HW + y * 48;
                ob[co * HW + x1] = acc[m][nt][0];
                ob[(co + 1) * HW + x1] = acc[m][nt][1];
                ob[co * HW + x2] = acc[m][nt][2];
                ob[(co + 1) * HW + x2] = acc[m][nt][3];
            }
        }
    }
}

// ---------------- flash attention: tf32 QK, f16 PV (unchanged from passing R4) ----------------
#define QS 68
#define KS 68
#define VS 136
#define SK_OFF 8704
#define SV_OFF (8704 + 2 * 8704)
#define ATTN_SMEM (SV_OFF * 4 + 2 * 9792 * 2)

__global__ void __launch_bounds__(256) attn_k(const float* __restrict__ tau) {
    extern __shared__ float sm[];
    float* sQ = sm;
    float* sK = sm + SK_OFF;
    __half* sVh = (__half*)(sm + SV_OFF);

    int n = blockIdx.z, g = blockIdx.y;
    int head = n * GG + g;
    int q0 = blockIdx.x * 128;
    int t = threadIdx.x, w = t >> 5, lane = t & 31;
    int grp = lane >> 2, tg = lane & 3;
    int qb = w * 16;
    float tl = tau[g] * 1.44269504f;

    unsigned sK_u = (unsigned)__cvta_generic_to_shared(sK);
    unsigned sV_u = (unsigned)__cvta_generic_to_shared(sVh);

    for (int idx = t; idx < 8192; idx += 256) {
        int c = idx >> 7, qq = idx & 127;
        sQ[qq * QS + c] = g_q[(head * 64 + c) * HW + q0 + qq] * tl;
    }
    for (int idx = t; idx < 2 * 8 * VS; idx += 256) {
        int buf = idx / (8 * VS);
        int r = idx % (8 * VS);
        int row = 64 + r / VS, col = r % VS;
        sVh[buf * 9792 + row * VS + col] = __float2half(row == 64 ? 1.f : 0.f);
    }

    auto stage = [&](int ch, int buf) {
        int db = ch * 128;
        const float* ksrc = g_kt + ((size_t)head * KROWS + db) * 64;
        for (int idx = t; idx < 2048; idx += 256) {
            int d = idx >> 4, seg = idx & 15;
            cp16(sK_u + (buf * 8704 + d * KS + seg * 4) * 4, ksrc + d * 64 + seg * 4);
        }
        const __half* vsrc = g_vth + (size_t)head * 64 * VROWS + db;
        for (int idx = t; idx < 1024; idx += 256) {
            int c = idx >> 4, seg = idx & 15;
            cp16(sV_u + (buf * 9792 + c * VS + seg * 8) * 2, vsrc + (size_t)c * VROWS + seg * 8);
        }
    };

    stage(0, 0);
    CP_COMMIT();
    __syncthreads();

    float aQ[8][4];
#pragma unroll
    for (int kc = 0; kc < 8; kc++) {
        const float* p = &sQ[(qb + grp) * QS + kc * 8 + tg];
        aQ[kc][0] = p[0];
        aQ[kc][1] = p[8 * QS];
        aQ[kc][2] = p[4];
        aQ[kc][3] = p[8 * QS + 4];
    }

    float O[9][4];
#pragma unroll
    for (int nt = 0; nt < 9; nt++)
#pragma unroll
        for (int r = 0; r < 4; r++) O[nt][r] = 0.f;
    float m0 = -1e30f, m1 = -1e30f;

    const int nch = KROWS / 128;
    for (int ch = 0; ch < nch; ch++) {
        int buf = ch & 1;
        if (ch + 1 < nch) { stage(ch + 1, buf ^ 1); CP_COMMIT(); CP_WAIT(1); }
        else CP_WAIT(0);
        __syncthreads();

        const float* sKb = sK + buf * 8704;
        const __half* sVb = sVh + buf * 9792;

        float S[16][4];
#pragma unroll
        for (int nt = 0; nt < 16; nt++) {
            S[nt][0] = S[nt][1] = S[nt][2] = S[nt][3] = 0.f;
#pragma unroll
            for (int kc = 0; kc < 8; kc++) {
                const float* bp = &sKb[(nt * 8 + grp) * KS + kc * 8 + tg];
                mma_tf32(S[nt], aQ[kc], bp[0], bp[4]);
            }
        }

        if (ch == nch - 1) {
            int cb = ch * 128 + 2 * tg;
#pragma unroll
            for (int nt = 0; nt < 16; nt++) {
                int c = cb + nt * 8;
                if (c >= DD)     { S[nt][0] = -1e30f; S[nt][2] = -1e30f; }
                if (c + 1 >= DD) { S[nt][1] = -1e30f; S[nt][3] = -1e30f; }
            }
        }

        float rm0 = -1e30f, rm1 = -1e30f;
#pragma unroll
        for (int nt = 0; nt < 16; nt++) {
            rm0 = fmaxf(rm0, fmaxf(S[nt][0], S[nt][1]));
            rm1 = fmaxf(rm1, fmaxf(S[nt][2], S[nt][3]));
        }
        rm0 = fmaxf(rm0, __shfl_xor_sync(0xffffffffu, rm0, 1));
        rm0 = fmaxf(rm0, __shfl_xor_sync(0xffffffffu, rm0, 2));
        rm1 = fmaxf(rm1, __shfl_xor_sync(0xffffffffu, rm1, 1));
        rm1 = fmaxf(rm1, __shfl_xor_sync(0xffffffffu, rm1, 2));
        float mn0 = fmaxf(m0, rm0), mn1 = fmaxf(m1, rm1);
        float a0 = ex2f(m0 - mn0), a1 = ex2f(m1 - mn1);
        m0 = mn0; m1 = mn1;
#pragma unroll
        for (int nt = 0; nt < 9; nt++) {
            O[nt][0] *= a0; O[nt][1] *= a0;
            O[nt][2] *= a1; O[nt][3] *= a1;
        }

        unsigned pf[16][2];
#pragma unroll
        for (int nt = 0; nt < 16; nt++) {
            pf[nt][0] = exp2h2(S[nt][0] - m0, S[nt][1] - m0);
            pf[nt][1] = exp2h2(S[nt][2] - m1, S[nt][3] - m1);
        }

#pragma unroll
        for (int kc = 0; kc < 8; kc++) {
            unsigned A4[4] = {pf[2 * kc][0], pf[2 * kc][1], pf[2 * kc + 1][0], pf[2 * kc + 1][1]};
#pragma unroll
            for (int nt = 0; nt < 9; nt++) {
                const __half* vp = &sVb[(nt * 8 + grp) * VS + kc * 16 + 2 * tg];
                unsigned b0 = *(const unsigned*)vp;
                unsigned b1 = *(const unsigned*)(vp + 8);
                mma_f16(O[nt], A4, b0, b1);
            }
        }
        __syncthreads();
    }

    float l0 = __shfl_sync(0xffffffffu, O[8][0], lane & ~3);
    float l1 = __shfl_sync(0xffffffffu, O[8][2], lane & ~3);
    float inv0 = 1.f / l0, inv1 = 1.f / l1;
#pragma unroll
    for (int nt = 0; nt < 8; nt++) {
        int c = nt * 8 + 2 * tg;
        float2 v0 = {O[nt][0] * inv0, O[nt][1] * inv0};
        float2 v1 = {O[nt][2] * inv1, O[nt][3] * inv1};
        *(float2*)&g_at[((size_t)head * HW + q0 + qb + grp) * 64 + c] = v0;
        *(float2*)&g_at[((size_t)head * HW + q0 + qb + grp + 8) * 64 + c] = v1;
    }
}

// ---------------- final: gate 1x1 + bias + gx + LSTM update ----------------
__device__ __forceinline__ float tanh_fast(float x) {
    float e = __expf(-2.f * fabsf(x));
    float r = (1.f - e) / (1.f + e);
    return copysignf(r, x);
}

__global__ void __launch_bounds__(256) final_k(const float* __restrict__ c_in,
                                               const float* __restrict__ b_i,
                                               const float* __restrict__ b_f,
                                               const float* __restrict__ b_g,
                                               const float* __restrict__ b_o,
                                               float* __restrict__ out) {
    extern __shared__ float s_wa[];
    int n = blockIdx.z, g = blockIdx.y, pxt = blockIdx.x;
    int t = threadIdx.x;
    int head = n * GG + g;
    int px = pxt * 256 + t;

    const float* wa_flat = (const float*)g_wa;
    for (int idx = t; idx < 4 * 64 * 64; idx += 256) {
        int s = idx >> 12, r = idx & 4095;
        s_wa[idx] = wa_flat[s * (GG * 4096) + g * 4096 + r];
    }
    __syncthreads();

    float av[64];
    const float4* ap = (const float4*)&g_at[((size_t)head * HW + px) * 64];
#pragma unroll
    for (int c4 = 0; c4 < 16; c4++) {
        float4 v = ap[c4];
        av[c4 * 4 + 0] = v.x;
        av[c4 * 4 + 1] = v.y;
        av[c4 * 4 + 2] = v.z;
        av[c4 * 4 + 3] = v.w;
    }

    for (int co = 0; co < 64; co++) {
        float ai = 0.f, af = 0.f, ag = 0.f, ao = 0.f;
#pragma unroll 16
        for (int ci = 0; ci < 64; ci++) {
            float a = av[ci];
            ai += s_wa[0 * 4096 + ci * 64 + co] * a;
            af += s_wa[1 * 4096 + ci * 64 + co] * a;
            ag += s_wa[2 * 4096 + ci * 64 + co] * a;
            ao += s_wa[3 * 4096 + ci * 64 + co] * a;
        }
        int ch = g * 64 + co;
        int gi = (n * 512 + ch) * HW + px;
        ai += b_i[ch] + g_gx[0][gi];
        af += b_f[ch] + g_gx[1][gi];
        ag += b_g[ch] + g_gx[2][gi];
        ao += b_o[ch] + g_gx[3][gi];
        float iv = 1.f / (1.f + __expf(-ai));
        float fv = 1.f / (1.f + __expf(-af));
        float gv = tanh_fast(ag);
        float ov = 1.f / (1.f + __expf(-ao));
        float cn = fv * c_in[gi] + iv * gv;
        out[gi] = ov * tanh_fast(cn);
    }
}

// ---------------- launch ----------------
extern "C" void kernel_launch(void* const* d_in, const int* in_sizes, int n_in,
                              void* d_out, int out_size) {
    const float* x_in = (const float*)d_in[0];
    const float* h    = (const float*)d_in[1];
    const float* c    = (const float*)d_in[2];
    const float* tau  = (const float*)d_in[3];
    const float* W_x  = (const float*)d_in[4];
    const float* W_ig = (const float*)d_in[5];
    const float* W_q  = (const float*)d_in[6];
    const float* W_k  = (const float*)d_in[7];
    const float* W_v  = (const float*)d_in[8];
    const float* Wi_a = (const float*)d_in[9];
    const float* Wi_x = (const float*)d_in[10];
    const float* b_i  = (const float*)d_in[11];
    const float* Wf_a = (const float*)d_in[12];
    const float* Wf_x = (const float*)d_in[13];
    const float* b_f  = (const float*)d_in[14];
    const float* Wg_a = (const float*)d_in[15];
    const float* Wg_x = (const float*)d_in[16];
    const float* b_g  = (const float*)d_in[17];
    const float* Wo_a = (const float*)d_in[18];
    const float* Wo_x = (const float*)d_in[19];
    const float* b_o  = (const float*)d_in[20];
    float* out = (float*)d_out;

    cudaFuncSetAttribute(attn_k, cudaFuncAttributeMaxDynamicSharedMemorySize, ATTN_SMEM);
    cudaFuncSetAttribute(conv3mma_k, cudaFuncAttributeMaxDynamicSharedMemorySize, CONV_SMEM);
    cudaFuncSetAttribute(final_k, cudaFuncAttributeMaxDynamicSharedMemorySize, 4 * 64 * 64 * 4);

    zero_pad_k<<<(NB * GG * (KROWS - DD) * 64 + 255) / 256, 256>>>();
    prep_wproj_k<<<(768 * 512 + 255) / 256, 256>>>(W_x, W_ig);
    prep_wc_all_k<<<dim3((8 * 128 * 9 * 64 + 255) / 256, 7), 256>>>(W_q, W_k, W_v,
                                                                    Wi_x, Wf_x, Wg_x, Wo_x);
    prep_wa_all_k<<<dim3((8 * 64 * 64 + 255) / 256, 4), 256>>>(Wi_a, Wf_a, Wg_a, Wo_a);

    copy_hxT_k<<<dim3(9, GG, NB), 256>>>(h);
    projmma_k<<<dim3(18, 8, NB), 256>>>(x_in, h);

    conv3mma_k<<<dim3(9, GG, NB * 5), 256, CONV_SMEM>>>(0);   // q + 4 gates
    conv3mma_k<<<dim3(9, GG, NB * 2), 256, CONV_SMEM>>>(1);   // k, v

    attn_k<<<dim3(HW / 128, GG, NB), 256, ATTN_SMEM>>>(tau);

    final_k<<<dim3(9, GG, NB), 256, 4 * 64 * 64 * 4>>>(c, b_i, b_f, b_g, b_o, out);
}